// round 9
// baseline (speedup 1.0000x reference)
#include <cuda_runtime.h>
#include <cstdint>

// Problem constants (match reference setup_inputs)
#define FEAT        128

// Tuning
#define ROWS_PER_WARP   128
#define WARPS_PER_BLOCK 8
#define BLOCK_THREADS   (WARPS_PER_BLOCK * 32)

// ---------------------------------------------------------------------------
// PDL primitives
// ---------------------------------------------------------------------------
__device__ __forceinline__ void pdl_trigger() {
    asm volatile("griddepcontrol.launch_dependents;" ::: "memory");
}
__device__ __forceinline__ void pdl_wait() {
    asm volatile("griddepcontrol.wait;" ::: "memory");
}

// 256-bit global load (sm_100+): 8 consecutive floats per lane.
__device__ __forceinline__ void ldg256(const float* __restrict__ p, float* v) {
    asm volatile("ld.global.v8.f32 {%0,%1,%2,%3,%4,%5,%6,%7}, [%8];"
                 : "=f"(v[0]), "=f"(v[1]), "=f"(v[2]), "=f"(v[3]),
                   "=f"(v[4]), "=f"(v[5]), "=f"(v[6]), "=f"(v[7])
                 : "l"(p));
}

// ---------------------------------------------------------------------------
// Kernel 1 (prologue): zero the output, then signal dependents (PDL).
// ---------------------------------------------------------------------------
__global__ void prologue_kernel(float4* __restrict__ out, int n4) {
    int i = blockIdx.x * blockDim.x + threadIdx.x;
    if (i < n4) out[i] = make_float4(0.f, 0.f, 0.f, 0.f);
    pdl_trigger();
}

// ---------------------------------------------------------------------------
// Kernel 2: sorted segment sum with LDG.256.
// One warp owns ROWS_PER_WARP contiguous rows. One 256-bit load covers TWO
// rows: lanes 0-15 take row r, lanes 16-31 take row r+1; each lane owns the
// 8 feature columns (lane&15)*8 .. +7. `cur` (the segment the lane's acc
// belongs to) is PER-LANE, so a boundary falling between the paired rows is
// handled naturally. Fast path (whole 8-row group in one segment, ~86% of
// groups): branch-free tree accumulate. Flush = 8 atomicAdds per lane.
// ---------------------------------------------------------------------------
__device__ __forceinline__ void flush_acc(float* __restrict__ out,
                                          int seg, int feat_base,
                                          const float* acc, int max_seg,
                                          bool& synced) {
    if (!synced) { pdl_wait(); synced = true; }
    if (seg < 0 || seg >= max_seg) return;  // insurance against bad ids
    float* p = out + (size_t)seg * FEAT + feat_base;
    #pragma unroll
    for (int k = 0; k < 8; ++k) atomicAdd(p + k, acc[k]);
}

__global__ __launch_bounds__(BLOCK_THREADS)
void seg_sum_kernel(const float* __restrict__ hf,    // [n_rows][FEAT] floats
                    const int* __restrict__ braw,    // batch, stride words
                    float* __restrict__ out,         // [max_seg][FEAT]
                    int n_rows, int max_seg) {
    const int warp_id   = blockIdx.x * WARPS_PER_BLOCK + (threadIdx.x >> 5);
    const int lane      = threadIdx.x & 31;
    const int half      = lane >> 4;            // 0: even row of pair, 1: odd
    const int feat_base = (lane & 15) * 8;

    // Inline dtype detect (warp-wide ballot over odd tail words).
    int didx = n_rows - 1 - 2 * lane;
    if (!(didx & 1)) didx -= 1;                 // force odd index
    int nz = (didx > 0) ? (braw[didx] != 0) : 0;
    const int stride = __any_sync(0xFFFFFFFF, nz) ? 1 : 2;

    int start = warp_id * ROWS_PER_WARP;
    if (start >= n_rows) return;
    int end = min(start + ROWS_PER_WARP, n_rows);

    bool synced = false;
    float acc[8];
    #pragma unroll
    for (int k = 0; k < 8; ++k) acc[k] = 0.f;
    int cur = braw[start * stride];             // per-lane segment tag

    int r = start;
    for (; r + 8 <= end; r += 8) {
        int s7 = braw[(r + 7) * stride];

        // 4 x LDG.256; load j covers rows (r+2j, r+2j+1).
        float v0[8], v1[8], v2[8], v3[8];
        const float* base = hf + (size_t)r * FEAT + half * FEAT + feat_base;
        ldg256(base + 0 * 2 * FEAT, v0);
        ldg256(base + 1 * 2 * FEAT, v1);
        ldg256(base + 2 * 2 * FEAT, v2);
        ldg256(base + 3 * 2 * FEAT, v3);

        if (__all_sync(0xFFFFFFFF, s7 == cur)) {
            // Fast path: whole group in one segment -> tree accumulate.
            #pragma unroll
            for (int k = 0; k < 8; ++k)
                acc[k] += (v0[k] + v1[k]) + (v2[k] + v3[k]);
        } else {
            // Slow path: per-pair logic with per-lane segment tags.
            float* vv[4] = {v0, v1, v2, v3};
            #pragma unroll
            for (int j = 0; j < 4; ++j) {
                int s_even = braw[(r + 2 * j + 0) * stride];
                int s_odd  = braw[(r + 2 * j + 1) * stride];
                int my_s = half ? s_odd : s_even;
                if (my_s != cur) {
                    flush_acc(out, cur, feat_base, acc, max_seg, synced);
                    cur = my_s;
                    #pragma unroll
                    for (int k = 0; k < 8; ++k) acc[k] = 0.f;
                }
                #pragma unroll
                for (int k = 0; k < 8; ++k) acc[k] += vv[j][k];
            }
        }
    }
    // Tail (< 8 rows): one row at a time, handled by lanes 0-15 only.
    for (; r < end; ++r) {
        if (half == 0) {
            int s = braw[r * stride];
            float tv[8];
            ldg256(hf + (size_t)r * FEAT + feat_base, tv);
            if (s != cur) {
                flush_acc(out, cur, feat_base, acc, max_seg, synced);
                cur = s;
                #pragma unroll
                for (int k = 0; k < 8; ++k) acc[k] = 0.f;
            }
            #pragma unroll
            for (int k = 0; k < 8; ++k) acc[k] += tv[k];
        }
    }
    // Final flush (per-lane segment tag).
    flush_acc(out, cur, feat_base, acc, max_seg, synced);
}

// ---------------------------------------------------------------------------
// Launch. Inputs: h_t (float32, N*FEAT) and batch (int32 or int64, N).
// Order disambiguated by element count (h_t is FEAT x larger).
// ---------------------------------------------------------------------------
extern "C" void kernel_launch(void* const* d_in, const int* in_sizes, int n_in,
                              void* d_out, int out_size) {
    int hi = 0, bi = 1;
    if (n_in >= 2 && in_sizes[0] < in_sizes[1]) { hi = 1; bi = 0; }

    const float* hf       = (const float*)d_in[hi];
    const int*   batchRaw = (const int*)d_in[bi];
    float*       out      = (float*)d_out;

    const int n_rows  = in_sizes[bi];
    const int max_seg = out_size / FEAT;

    // 1) zero output (signals PDL completion when done)
    int n4 = out_size / 4;
    prologue_kernel<<<(n4 + 255) / 256, 256>>>((float4*)d_out, n4);

    // 2) segment sum — PDL launch, overlaps with prologue
    int n_warps  = (n_rows + ROWS_PER_WARP - 1) / ROWS_PER_WARP;
    int n_blocks = (n_warps + WARPS_PER_BLOCK - 1) / WARPS_PER_BLOCK;

    cudaLaunchConfig_t cfg = {};
    cfg.gridDim  = dim3(n_blocks, 1, 1);
    cfg.blockDim = dim3(BLOCK_THREADS, 1, 1);
    cfg.dynamicSmemBytes = 0;
    cfg.stream = 0;
    cudaLaunchAttribute attrs[1];
    attrs[0].id = cudaLaunchAttributeProgrammaticStreamSerialization;
    attrs[0].val.programmaticStreamSerializationAllowed = 1;
    cfg.attrs = attrs;
    cfg.numAttrs = 1;
    cudaLaunchKernelEx(&cfg, seg_sum_kernel, hf, batchRaw, out, n_rows, max_seg);
}

// round 10
// speedup vs baseline: 1.0956x; 1.0956x over previous
#include <cuda_runtime.h>
#include <cstdint>

// Problem constants (match reference setup_inputs)
#define FEAT        128
#define MAX_SEGS    16384      // >= NUM_GRAPHS (10000), safety headroom

#define WARPS_PER_BLOCK 8
#define BLOCK_THREADS   (WARPS_PER_BLOCK * 32)

// Segment fencepost table: seg_start[g] = first row of segment g;
// seg_start[max_seg] = n_rows. Device-global scratch (no allocation allowed).
__device__ int g_seg_start[MAX_SEGS + 1];

// ---------------------------------------------------------------------------
// PDL primitives
// ---------------------------------------------------------------------------
__device__ __forceinline__ void pdl_trigger() {
    asm volatile("griddepcontrol.launch_dependents;" ::: "memory");
}
__device__ __forceinline__ void pdl_wait() {
    asm volatile("griddepcontrol.wait;" ::: "memory");
}

// ---------------------------------------------------------------------------
// Kernel 1 (prologue): build seg_start[] from the sorted batch array.
// Thread r (0..n): b0 = batch[r-1] (or -1), b1 = batch[r] (or max_seg at r=n);
// writes seg_start[g] = r for all g in (b0, b1]. Sorted input => each g is
// written exactly once; empty segments get the start of the next non-empty
// one (zero-length range). Dtype (int32 vs int64) detected per warp via
// ballot over odd tail words (int64 high halves are zero).
// ---------------------------------------------------------------------------
__global__ void prologue_kernel(const int* __restrict__ braw, int n,
                                int max_seg) {
    const int lane = threadIdx.x & 31;
    // dtype detect
    int didx = n - 1 - 2 * lane;
    if (!(didx & 1)) didx -= 1;
    int nz = (didx > 0) ? (braw[didx] != 0) : 0;
    const int stride = __any_sync(0xFFFFFFFF, nz) ? 1 : 2;

    for (int r = blockIdx.x * blockDim.x + threadIdx.x; r <= n;
         r += gridDim.x * blockDim.x) {
        int b0 = (r > 0) ? braw[(r - 1) * stride] : -1;
        int b1 = (r < n) ? braw[r * stride] : max_seg;
        // clamp (insurance against bad ids)
        if (b0 < -1) b0 = -1;
        if (b1 > max_seg) b1 = max_seg;
        for (int g = b0 + 1; g <= b1; ++g) g_seg_start[g] = r;
    }
    pdl_trigger();
}

// ---------------------------------------------------------------------------
// Kernel 2: segment-ownership sum. One warp per segment; each lane owns 4
// features (one float4 / LDG.128 per row). Streams the segment's contiguous
// row range with x8 unroll + tree accumulate, then writes the result with a
// single plain STG.128 per lane. No atomics, no output zeroing (every
// segment written exactly once; empty segments store zeros over the poison).
// ---------------------------------------------------------------------------
__global__ __launch_bounds__(BLOCK_THREADS)
void seg_sum_kernel(const float4* __restrict__ h,    // [n_rows][32] float4
                    float* __restrict__ out,         // [max_seg][FEAT]
                    int n_rows, int max_seg) {
    const int g    = blockIdx.x * WARPS_PER_BLOCK + (threadIdx.x >> 5);
    const int lane = threadIdx.x & 31;
    if (g >= max_seg) return;

    pdl_wait();  // seg_start must be complete

    int s = g_seg_start[g];
    int e = g_seg_start[g + 1];
    // insurance clamps
    if (s < 0) s = 0;
    if (e > n_rows) e = n_rows;

    float4 acc = make_float4(0.f, 0.f, 0.f, 0.f);

    int r = s;
    for (; r + 8 <= e; r += 8) {
        float4 v[8];
        #pragma unroll
        for (int j = 0; j < 8; ++j)
            v[j] = __ldcs(&h[(size_t)(r + j) * 32 + lane]);

        // Tree-sum: single dependency on acc.
        float4 t01, t23, t45, t67, t03, t47, t;
        t01.x = v[0].x + v[1].x; t01.y = v[0].y + v[1].y; t01.z = v[0].z + v[1].z; t01.w = v[0].w + v[1].w;
        t23.x = v[2].x + v[3].x; t23.y = v[2].y + v[3].y; t23.z = v[2].z + v[3].z; t23.w = v[2].w + v[3].w;
        t45.x = v[4].x + v[5].x; t45.y = v[4].y + v[5].y; t45.z = v[4].z + v[5].z; t45.w = v[4].w + v[5].w;
        t67.x = v[6].x + v[7].x; t67.y = v[6].y + v[7].y; t67.z = v[6].z + v[7].z; t67.w = v[6].w + v[7].w;
        t03.x = t01.x + t23.x; t03.y = t01.y + t23.y; t03.z = t01.z + t23.z; t03.w = t01.w + t23.w;
        t47.x = t45.x + t67.x; t47.y = t45.y + t67.y; t47.z = t45.z + t67.z; t47.w = t45.w + t67.w;
        t.x = t03.x + t47.x; t.y = t03.y + t47.y; t.z = t03.z + t47.z; t.w = t03.w + t47.w;
        acc.x += t.x; acc.y += t.y; acc.z += t.z; acc.w += t.w;
    }
    for (; r < e; ++r) {
        float4 vv = __ldcs(&h[(size_t)r * 32 + lane]);
        acc.x += vv.x; acc.y += vv.y; acc.z += vv.z; acc.w += vv.w;
    }

    // One coalesced 512B store per warp (plain, cached).
    float4* op = (float4*)(out + (size_t)g * FEAT) + lane;
    *op = acc;
}

// ---------------------------------------------------------------------------
// Launch. Inputs: h_t (float32, N*FEAT) and batch (int32 or int64, N).
// Order disambiguated by element count (h_t is FEAT x larger).
// ---------------------------------------------------------------------------
extern "C" void kernel_launch(void* const* d_in, const int* in_sizes, int n_in,
                              void* d_out, int out_size) {
    int hi = 0, bi = 1;
    if (n_in >= 2 && in_sizes[0] < in_sizes[1]) { hi = 1; bi = 0; }

    const float4* h        = (const float4*)d_in[hi];
    const int*    batchRaw = (const int*)d_in[bi];
    float*        out      = (float*)d_out;

    const int n_rows  = in_sizes[bi];
    int max_seg = out_size / FEAT;
    if (max_seg > MAX_SEGS) max_seg = MAX_SEGS;

    // 1) fencepost build (PDL-triggering)
    int n_thr = n_rows + 1;
    prologue_kernel<<<(n_thr + 255) / 256, 256>>>(batchRaw, n_rows, max_seg);

    // 2) one warp per segment — PDL launch
    int n_blocks = (max_seg + WARPS_PER_BLOCK - 1) / WARPS_PER_BLOCK;

    cudaLaunchConfig_t cfg = {};
    cfg.gridDim  = dim3(n_blocks, 1, 1);
    cfg.blockDim = dim3(BLOCK_THREADS, 1, 1);
    cfg.dynamicSmemBytes = 0;
    cfg.stream = 0;
    cudaLaunchAttribute attrs[1];
    attrs[0].id = cudaLaunchAttributeProgrammaticStreamSerialization;
    attrs[0].val.programmaticStreamSerializationAllowed = 1;
    cfg.attrs = attrs;
    cfg.numAttrs = 1;
    cudaLaunchKernelEx(&cfg, seg_sum_kernel, h, out, n_rows, max_seg);
}